// round 15
// baseline (speedup 1.0000x reference)
#include <cuda_runtime.h>
#include <cuda_bf16.h>
#include <cuda_fp16.h>
#include <math.h>
#include <stdint.h>

#define T_STEPS 24
#define NN 50000
#define NPAD 50048
#define EE 1600000
#define F 16
#define H 64
#define LH 128
#define SCAN_NB 98

#define MTILE 32
#define NTILES (NPAD / MTILE)     // 1564
#define NCTAS 148
#define NPROD (NCTAS * 8)         // 1184 producer warps

// fused kernel smem layout
#define BOFF 0                    // B fp16: 512 x 400 = 204800
#define AOFF 204800               // A: 32 x 400 = 12800
#define W2HOFF 217600             // W2 fp16: 64*64*2 = 8192
#define B2OFF 225792              // b2: 256
#define BIASOFF 226048            // bias: 512 f32 = 2048
#define W1HOFF 228096             // W1 fp16: 16*64*2 = 2048
#define B1OFF 230144              // b1: 256
#define FUSED_SMEM 230400

// ---------------- helpers ----------------
__device__ __forceinline__ uint32_t smem_u32(const void* p) {
    uint32_t a;
    asm("{ .reg .u64 t; cvta.to.shared.u64 t, %1; cvt.u32.u64 %0, t; }" : "=r"(a) : "l"(p));
    return a;
}
__device__ __forceinline__ void ldsm4(uint32_t* r, uint32_t addr) {
    asm volatile("ldmatrix.sync.aligned.m8n8.x4.shared.b16 {%0,%1,%2,%3}, [%4];"
                 : "=r"(r[0]), "=r"(r[1]), "=r"(r[2]), "=r"(r[3]) : "r"(addr));
}
__device__ __forceinline__ void mma16816(float* c, const uint32_t* a, const uint32_t* b) {
    asm volatile(
        "mma.sync.aligned.m16n8k16.row.col.f32.f16.f16.f32 "
        "{%0,%1,%2,%3}, {%4,%5,%6,%7}, {%8,%9}, {%0,%1,%2,%3};"
        : "+f"(c[0]), "+f"(c[1]), "+f"(c[2]), "+f"(c[3])
        : "r"(a[0]), "r"(a[1]), "r"(a[2]), "r"(a[3]), "r"(b[0]), "r"(b[1]));
}
__device__ __forceinline__ void cp16(uint32_t dst, const void* src) {
    asm volatile("cp.async.cg.shared.global [%0], [%1], 16;" :: "r"(dst), "l"(src));
}
__device__ __forceinline__ float tanha(float x) {
    float r;
    asm("tanh.approx.f32 %0, %1;" : "=f"(r) : "f"(x));
    return r;
}
__device__ __forceinline__ float sigt(float x) {
    return fmaf(tanha(0.5f * x), 0.5f, 0.5f);
}
__device__ __forceinline__ void acc8(float* a, uint4 v) {
    __half2* h = (__half2*)&v;
    #pragma unroll
    for (int i = 0; i < 4; i++) {
        float2 p = __half22float2(h[i]);
        a[2 * i] += p.x; a[2 * i + 1] += p.y;
    }
}
__device__ __forceinline__ unsigned ld_acq(const unsigned* p) {
    unsigned v;
    asm volatile("ld.acquire.gpu.global.u32 %0, [%1];" : "=r"(v) : "l"(p) : "memory");
    return v;
}
#define BAR_LSTM() asm volatile("bar.sync 1, 256;" ::: "memory")

// ---------------- scratch ----------------
__device__ int   d_deg[NN];
__device__ int   d_rowptr[NN + 1];
__device__ int   d_cursor[NN];
__device__ int   d_csr[EE];
__device__ int   d_blocksum[128];
__device__ float d_dinv[NN];
__device__ unsigned d_flags[16];                  // [0..5]=h2 chunk done, [8..10]=h1 chunk done
__device__ __half d_xh[19200000];                 // [n][t*16+c]  (x * dinv[n])
__device__ __half d_h1[76800000];                 // [q][n][4t][64]   (h1 * dinv[n])
__device__ __half d_h2[76873728];                 // [t][NPAD][64] fp16
__device__ __half d_hst[6406144];                 // h state spill [NPAD][128]
__device__ float d_cst[6406144];                  // c state spill [tile][tid][16]
__device__ uint4 d_Bp[512 * 24];                  // fp16 weights, reordered cols

// ---------------- CSR build ----------------
__global__ void deg_kernel(const int* __restrict__ ei) {
    int e = blockIdx.x * 256 + threadIdx.x;
    if (e < EE) atomicAdd(&d_deg[ei[EE + e]], 1);
}
__global__ void dinv_scan_kernel() {
    __shared__ int s[512];
    int tid = threadIdx.x;
    int i = blockIdx.x * 512 + tid;
    int v = (i < NN) ? d_deg[i] : 0;
    if (i < NN) d_dinv[i] = rsqrtf((float)v + 1.0f);
    s[tid] = v;
    __syncthreads();
    #pragma unroll
    for (int off = 1; off < 512; off <<= 1) {
        int t = (tid >= off) ? s[tid - off] : 0;
        __syncthreads();
        s[tid] += t;
        __syncthreads();
    }
    if (i < NN) d_rowptr[i + 1] = s[tid];
    if (tid == 511) d_blocksum[blockIdx.x] = s[511];
}
__global__ void scan_add2_kernel() {
    __shared__ int soff;
    int sbk = blockIdx.x >> 1;
    if (threadIdx.x == 0) {
        int o = 0;
        for (int j = 0; j < sbk; j++) o += d_blocksum[j];
        soff = o;
    }
    __syncthreads();
    int i = blockIdx.x * 256 + threadIdx.x;
    if (i == 0) { d_rowptr[0] = 0; d_cursor[0] = 0; }
    if (i < NN) {
        int v = d_rowptr[i + 1] + soff;
        d_rowptr[i + 1] = v;
        if (i + 1 < NN) d_cursor[i + 1] = v;
    }
}

// ---------------- fused fill: csr_fill + xprep + bprep ----------------
__global__ void fused_fill_kernel(const int* __restrict__ ei,
                                  const float* __restrict__ x_seq,
                                  const float* __restrict__ Wih,
                                  const float* __restrict__ Whh) {
    int b = blockIdx.x;
    if (b < 6250) {
        int e = b * 256 + threadIdx.x;
        int s = ei[e];
        int d = ei[EE + e];
        int idx = atomicAdd(&d_cursor[d], 1);
        d_csr[idx] = s;
    } else if (b < 25000) {
        int id = (b - 6250) * 256 + threadIdx.x;
        if (id >= NN * 96) return;
        int n = id / 96, r = id % 96;
        int t = r >> 2, c4 = r & 3;
        float dn = d_dinv[n];
        float4 v = *(const float4*)(x_seq + ((size_t)t * NN + n) * F + c4 * 4);
        __half h[4] = {__float2half_rn(v.x * dn), __float2half_rn(v.y * dn),
                       __float2half_rn(v.z * dn), __float2half_rn(v.w * dn)};
        *(uint2*)(d_xh + (size_t)n * 384 + r * 4) = *(uint2*)h;
    } else {
        int id = (b - 25000) * 256 + threadIdx.x;
        if (id >= 512 * 24) return;
        int cg = id / 24, u = id % 24;
        int nb = cg >> 7, c = cg & 127;
        int wn = c >> 6, g = (c >> 4) & 3, jh = (c >> 3) & 1, s = c & 7;
        int jg = nb * 32 + wn * 16 + jh * 8 + s;
        int G = g * 128 + jg;
        union { __half h[8]; uint4 q; } up;
        #pragma unroll
        for (int e = 0; e < 8; e++) {
            int k = u * 8 + e;
            float v = (k < 64) ? Wih[G * 64 + k] : Whh[G * 128 + (k - 64)];
            up.h[e] = __float2half_rn(v);
        }
        d_Bp[(size_t)cg * 24 + u] = up.q;
    }
}

// ---------------- fused pipeline: agg1 -> agg2 producers + tile LSTM + FC ----------------
__global__ void __launch_bounds__(512, 1) fused_lstm(
    const float* __restrict__ bih, const float* __restrict__ bhh,
    const float* __restrict__ W1, const float* __restrict__ b1,
    const float* __restrict__ W2, const float* __restrict__ b2,
    const float* __restrict__ Wf1, const float* __restrict__ bf1,
    const float* __restrict__ Wf2, const float* __restrict__ bf2,
    float* __restrict__ out) {
    extern __shared__ char smem[];
    uint32_t sb = smem_u32(smem);
    const int tid = threadIdx.x, lane = tid & 31, wid = tid >> 5;
    const int cta = blockIdx.x;

    // one-time smem init (all 512 threads)
    for (int i = tid; i < 512 * 24; i += 512) {
        int col = i / 24, u = i % 24;
        *(uint4*)(smem + BOFF + col * 400 + u * 16) = d_Bp[(size_t)col * 24 + u];
    }
    __half* W2h = (__half*)(smem + W2HOFF);
    for (int i = tid; i < H * H; i += 512) W2h[i] = __float2half_rn(W2[i]);
    __half* W1h = (__half*)(smem + W1HOFF);
    for (int i = tid; i < F * H; i += 512) W1h[i] = __float2half_rn(W1[i]);
    float* b2s = (float*)(smem + B2OFF);
    if (tid < H) b2s[tid] = b2[tid];
    float* b1s = (float*)(smem + B1OFF);
    if (tid < H) b1s[tid] = b1[tid];
    float* bs = (float*)(smem + BIASOFF);
    if (tid < 512) bs[tid] = bih[tid] + bhh[tid];
    __syncthreads();

    if (wid >= 8) {
        // ================== PRODUCER ==================
        int pw = cta * 8 + (wid - 8);          // 0..1183
        const uint2* xr = (const uint2*)d_xh;
        const int t8 = lane >> 2, c4 = lane & 3;

        // ---- phase 1: agg1 + mm1, three 8-t chunks ----
        for (int qq8 = 0; qq8 < 3; qq8++) {
            for (int n = pw; n < NN; n += NPROD) {
                float dn = d_dinv[n];
                size_t xbase = (size_t)n * 96 + qq8 * 32 + lane;
                uint2 u = xr[xbase];
                float2 p0 = __half22float2(*(__half2*)&u.x);
                float2 p1 = __half22float2(*(__half2*)&u.y);
                float a0 = p0.x, a1 = p0.y, a2 = p1.x, a3 = p1.y;
                int e = d_rowptr[n], e1 = d_rowptr[n + 1];
                for (; e + 8 <= e1; e += 8) {
                    int si[8];
                    #pragma unroll
                    for (int k = 0; k < 8; k++) si[k] = d_csr[e + k];
                    uint2 v[8];
                    #pragma unroll
                    for (int k = 0; k < 8; k++)
                        v[k] = xr[(size_t)si[k] * 96 + qq8 * 32 + lane];
                    #pragma unroll
                    for (int k = 0; k < 8; k++) {
                        float2 q0 = __half22float2(*(__half2*)&v[k].x);
                        float2 q1 = __half22float2(*(__half2*)&v[k].y);
                        a0 += q0.x; a1 += q0.y; a2 += q1.x; a3 += q1.y;
                    }
                }
                for (; e < e1; e++) {
                    uint2 v = xr[(size_t)d_csr[e] * 96 + qq8 * 32 + lane];
                    float2 q0 = __half22float2(*(__half2*)&v.x);
                    float2 q1 = __half22float2(*(__half2*)&v.y);
                    a0 += q0.x; a1 += q0.y; a2 += q1.x; a3 += q1.y;
                }
                float yv[4] = {a0 * dn, a1 * dn, a2 * dn, a3 * dn};
                // mm1: lane -> (t = t8, cols c4*16..c4*16+15)
                float o[16];
                #pragma unroll
                for (int jj = 0; jj < 16; jj++) o[jj] = b1s[c4 * 16 + jj];
                #pragma unroll
                for (int k = 0; k < 16; k++) {
                    float yk = __shfl_sync(0xffffffffu, yv[k & 3], (t8 << 2) | (k >> 2));
                    #pragma unroll
                    for (int jj = 0; jj < 16; jj++)
                        o[jj] = fmaf(yk, __half2float(W1h[k * 64 + c4 * 16 + jj]), o[jj]);
                }
                __half hp[16];
                #pragma unroll
                for (int jj = 0; jj < 16; jj++)
                    hp[jj] = __float2half_rn(fmaxf(o[jj], 0.0f) * dn);
                int tg = qq8 * 8 + t8;
                __half* dst = d_h1 + (((size_t)(tg >> 2) * NN + n) * 4 + (tg & 3)) * 64 + c4 * 16;
                *(uint4*)dst = *(uint4*)hp;
                *(uint4*)(dst + 8) = *(uint4*)(hp + 8);
            }
            __threadfence();
            __syncwarp();
            if (lane == 0) atomicAdd(&d_flags[8 + qq8], 1u);
        }

        // ---- phase 2: agg2 + mm2, six 4-t chunks gated on h1 chunks ----
        int tt_o = lane >> 3, j8 = lane & 7, j0 = j8 * 8;
        float b2r[8];
        #pragma unroll
        for (int jj = 0; jj < 8; jj++) b2r[jj] = b2s[j0 + jj];
        for (int q = 0; q < 6; q++) {
            int qq8 = q >> 1;
            if (lane == 0) {
                while (ld_acq(&d_flags[8 + qq8]) < (unsigned)NPROD)
                    asm volatile("nanosleep.u32 128;");
            }
            __syncwarp();
            const uint4* h1q = (const uint4*)d_h1 + (size_t)q * NN * 32;
            for (int n = pw; n < NN; n += NPROD) {
                float dn = d_dinv[n];
                float acc[8];
                {
                    uint4 sv = h1q[(size_t)n * 32 + lane];
                    __half2* h = (__half2*)&sv;
                    #pragma unroll
                    for (int i = 0; i < 4; i++) {
                        float2 p = __half22float2(h[i]);
                        acc[2 * i] = p.x; acc[2 * i + 1] = p.y;
                    }
                }
                int e = d_rowptr[n], e1 = d_rowptr[n + 1];
                for (; e + 8 <= e1; e += 8) {
                    int si[8];
                    #pragma unroll
                    for (int u2 = 0; u2 < 8; u2++) si[u2] = d_csr[e + u2];
                    uint4 v[8];
                    #pragma unroll
                    for (int u2 = 0; u2 < 8; u2++) v[u2] = h1q[(size_t)si[u2] * 32 + lane];
                    #pragma unroll
                    for (int u2 = 0; u2 < 8; u2++) acc8(acc, v[u2]);
                }
                for (; e < e1; e++)
                    acc8(acc, h1q[(size_t)d_csr[e] * 32 + lane]);
                #pragma unroll
                for (int i = 0; i < 8; i++) acc[i] *= dn;
                float o[8];
                #pragma unroll
                for (int jj = 0; jj < 8; jj++) o[jj] = b2r[jj];
                #pragma unroll 8
                for (int k = 0; k < 64; k++) {
                    float zk = __shfl_sync(0xffffffffu, acc[k & 7],
                                           (lane & 24) + (k >> 3));
                    uint4 wv = *(uint4*)(W2h + k * 64 + j0);
                    __half2* wh = (__half2*)&wv;
                    #pragma unroll
                    for (int i = 0; i < 4; i++) {
                        float2 wp = __half22float2(wh[i]);
                        o[2 * i] = fmaf(zk, wp.x, o[2 * i]);
                        o[2 * i + 1] = fmaf(zk, wp.y, o[2 * i + 1]);
                    }
                }
                __half hp[8];
                #pragma unroll
                for (int jj = 0; jj < 8; jj++)
                    hp[jj] = __float2half_rn(fmaxf(o[jj], 0.0f));
                *(uint4*)(d_h2 + ((size_t)(q * 4 + tt_o) * NPAD + n) * 64 + j0) = *(uint4*)hp;
            }
            __threadfence();
            __syncwarp();
            if (lane == 0) atomicAdd(&d_flags[q], 1u);
        }

        // ---- tail: zero d_deg for the next graph replay ----
        for (int i = pw * 32 + lane; i < NN; i += NPROD * 32) d_deg[i] = 0;
        return;
    }

    // ================== CONSUMER: tile LSTM, chunk-major ==================
    const int ntile = (cta < NTILES - NCTAS * 10) ? 11 : 10;   // 1564 = 84*11 + 64*10
    const int gq = lane >> 2, tq = lane & 3;
    const int q4 = lane >> 3, r8 = lane & 7;
    const uint32_t aRowOff = (uint32_t)(((q4 & 1) * 8 + r8) * 400 + ((q4 >> 1) * 8) * 2);
    const uint32_t bRowBase = (uint32_t)((wid * 64 + (q4 >> 1) * 8 + r8) * 400 + (q4 & 1) * 16);

    for (int q = 0; q < 6; q++) {
        if (tid == 0) {
            while (ld_acq(&d_flags[q]) < (unsigned)NPROD)
                asm volatile("nanosleep.u32 128;");
        }
        BAR_LSTM();

        for (int k = 0; k < ntile; k++) {
            int tile = cta + k * NCTAS;
            int row0 = tile * MTILE;
            // stage h2(q*4): 32 rows x 128B
            {
                int row = tid >> 3, u = tid & 7;
                cp16(sb + AOFF + row * 400 + u * 16,
                     d_h2 + ((size_t)(q * 4) * NPAD + row0 + row) * 64 + u * 8);
            }
            asm volatile("cp.async.commit_group;" ::: "memory");
            // state: c regs + h smem section (32 rows x 256B = 512 uint4)
            float creg[16];
            if (q == 0) {
                #pragma unroll
                for (int i = 0; i < 16; i++) creg[i] = 0.0f;
                for (int i = tid; i < 512; i += 256) {
                    int row = i >> 4, u = i & 15;
                    *(uint4*)(smem + AOFF + row * 400 + 128 + u * 16) =
                        make_uint4(0, 0, 0, 0);
                }
            } else {
                const float4* cp4 = (const float4*)(d_cst + ((size_t)tile * 256 + tid) * 16);
                #pragma unroll
                for (int i = 0; i < 4; i++) {
                    float4 v = cp4[i];
                    creg[4 * i] = v.x; creg[4 * i + 1] = v.y;
                    creg[4 * i + 2] = v.z; creg[4 * i + 3] = v.w;
                }
                for (int i = tid; i < 512; i += 256) {
                    int row = i >> 4, u = i & 15;
                    *(uint4*)(smem + AOFF + row * 400 + 128 + u * 16) =
                        *(const uint4*)(d_hst + (size_t)(row0 + row) * 128 + u * 8);
                }
            }
            asm volatile("cp.async.wait_group 0;" ::: "memory");
            BAR_LSTM();

            for (int t = q * 4; t < q * 4 + 4; t++) {
                float acc[2][8][4];
                #pragma unroll
                for (int mi = 0; mi < 2; mi++)
                    #pragma unroll
                    for (int nt = 0; nt < 8; nt++)
                        #pragma unroll
                        for (int r = 0; r < 4; r++) acc[mi][nt][r] = 0.0f;

                uint32_t aB = sb + AOFF + aRowOff;
                uint32_t bB = sb + BOFF + bRowBase;
                #pragma unroll 1
                for (int ks = 0; ks < 12; ks++) {
                    uint32_t a[2][4];
                    ldsm4(a[0], aB + ks * 32);
                    ldsm4(a[1], aB + 16 * 400 + ks * 32);
                    #pragma unroll
                    for (int pr = 0; pr < 4; pr++) {
                        uint32_t t4[4];
                        ldsm4(t4, bB + pr * (16 * 400) + ks * 32);
                        uint32_t b0[2] = {t4[0], t4[1]};
                        uint32_t b1v[2] = {t4[2], t4[3]};
                        #pragma unroll
                        for (int mi = 0; mi < 2; mi++) {
                            mma16816(acc[mi][2 * pr], a[mi], b0);
                            mma16816(acc[mi][2 * pr + 1], a[mi], b1v);
                        }
                    }
                }
                BAR_LSTM();

                // prefetch h2(t+1) within chunk
                if (t + 1 < q * 4 + 4) {
                    int row = tid >> 3, u = tid & 7;
                    cp16(sb + AOFF + row * 400 + u * 16,
                         d_h2 + ((size_t)(t + 1) * NPAD + row0 + row) * 64 + u * 8);
                }
                asm volatile("cp.async.commit_group;" ::: "memory");

                // epilogue
                #pragma unroll
                for (int mi = 0; mi < 2; mi++) {
                    #pragma unroll
                    for (int h = 0; h < 2; h++) {
                        int rl = mi * 16 + h * 8 + gq;
                        #pragma unroll
                        for (int jh = 0; jh < 2; jh++) {
                            int jl0 = jh * 8 + 2 * tq;
                            int jg0 = (wid >> 1) * 32 + (wid & 1) * 16 + jl0;
                            __half hout[2];
                            #pragma unroll
                            for (int p = 0; p < 2; p++) {
                                int jg = jg0 + p;
                                int ci = h * 2 + p;
                                float gi = acc[mi][0 + jh][ci] + bs[jg];
                                float gf = acc[mi][2 + jh][ci] + bs[128 + jg];
                                float gG = acc[mi][4 + jh][ci] + bs[256 + jg];
                                float go = acc[mi][6 + jh][ci] + bs[384 + jg];
                                int cidx = mi * 8 + h * 4 + jh * 2 + p;
                                float cn = sigt(gf) * creg[cidx] + sigt(gi) * tanha(gG);
                                creg[cidx] = cn;
                                hout[p] = __float2half_rn(sigt(go) * tanha(cn));
                            }
                            *(uint*)(smem + AOFF + rl * 400 + 128 + jg0 * 2) = *(uint*)hout;
                        }
                    }
                }
                asm volatile("cp.async.wait_group 0;" ::: "memory");
                BAR_LSTM();
            }

            if (q < 5) {
                // spill state: c regs + full h section (512 uint4)
                float4* cp4 = (float4*)(d_cst + ((size_t)tile * 256 + tid) * 16);
                #pragma unroll
                for (int i = 0; i < 4; i++)
                    cp4[i] = make_float4(creg[4 * i], creg[4 * i + 1],
                                         creg[4 * i + 2], creg[4 * i + 3]);
                for (int i = tid; i < 512; i += 256) {
                    int row = i >> 4, u = i & 15;
                    *(uint4*)(d_hst + (size_t)(row0 + row) * 128 + u * 8) =
                        *(const uint4*)(smem + AOFF + row * 400 + 128 + u * 16);
                }
            } else {
                // fused FC head from smem h
                int node = tid >> 3, e8 = tid & 7;
                const __half* hrow = (const __half*)(smem + AOFF + node * 400 + 128);
                float part = 0.0f;
                #pragma unroll
                for (int jj = 0; jj < 4; jj++) {
                    int j = e8 * 4 + jj;
                    float z = __ldg(bf1 + j);
                    #pragma unroll 8
                    for (int kk = 0; kk < 128; kk++)
                        z = fmaf(__half2float(hrow[kk]), __ldg(Wf1 + kk * 32 + j), z);
                    part = fmaf(fmaxf(z, 0.0f), __ldg(Wf2 + j), part);
                }
                #pragma unroll
                for (int off = 4; off > 0; off >>= 1)
                    part += __shfl_down_sync(0xffffffffu, part, off, 8);
                int n = row0 + node;
                if (e8 == 0 && n < NN) out[n] = part + __ldg(bf2);
                BAR_LSTM();
            }
        }
    }
}

// ---------------- launcher ----------------
extern "C" void kernel_launch(void* const* d_in, const int* in_sizes, int n_in,
                              void* d_out, int out_size) {
    const float* x_seq = (const float*)d_in[0];
    const int*   ei    = (const int*)d_in[1];
    const float* W1    = (const float*)d_in[2];
    const float* b1    = (const float*)d_in[3];
    const float* W2    = (const float*)d_in[4];
    const float* b2    = (const float*)d_in[5];
    const float* Wih   = (const float*)d_in[6];
    const float* Whh   = (const float*)d_in[7];
    const float* bih   = (const float*)d_in[8];
    const float* bhh   = (const float*)d_in[9];
    const float* Wf1   = (const float*)d_in[10];
    const float* bf1   = (const float*)d_in[11];
    const float* Wf2   = (const float*)d_in[12];
    const float* bf2   = (const float*)d_in[13];
    float* out = (float*)d_out;

    cudaFuncSetAttribute(fused_lstm, cudaFuncAttributeMaxDynamicSharedMemorySize,
                         FUSED_SMEM);

    void* flagsp;
    cudaGetSymbolAddress(&flagsp, d_flags);
    cudaMemsetAsync(flagsp, 0, 16 * sizeof(unsigned));     // launch 0

    deg_kernel<<<(EE + 255) / 256, 256>>>(ei);             // launch 1
    dinv_scan_kernel<<<SCAN_NB, 512>>>();                  // launch 2
    scan_add2_kernel<<<(NN + 255) / 256, 256>>>();         // launch 3
    fused_fill_kernel<<<25048, 256>>>(ei, x_seq, Wih, Whh);// launch 4
    fused_lstm<<<NCTAS, 512, FUSED_SMEM>>>(                // launch 5 (ncu -s 5 lands here)
        bih, bhh, W1, b1, W2, b2, Wf1, bf1, Wf2, bf2, out);
}

// round 16
// speedup vs baseline: 1.1528x; 1.1528x over previous
#include <cuda_runtime.h>
#include <cuda_bf16.h>
#include <cuda_fp16.h>
#include <math.h>
#include <stdint.h>

#define T_STEPS 24
#define NN 50000
#define NPAD 50048
#define EE 1600000
#define F 16
#define H 64
#define LH 128
#define SCAN_NB 98

#define MTILE 32
#define NTILES (NPAD / MTILE)     // 1564
#define NCTAS 148
#define NPROD (NCTAS * 8)         // 1184 producer warps

// fused kernel smem layout
#define BOFF 0                    // B fp16: 512 x 400 = 204800
#define AOFF 204800               // A: 32 x 400 = 12800
#define W2HOFF 217600             // W2 fp16: 64*64*2 = 8192
#define B2OFF 225792              // b2: 256
#define BIASOFF 226048            // bias: 512 f32 = 2048
#define W1HOFF 228096             // W1 fp16: 16*64*2 = 2048
#define B1OFF 230144              // b1: 256
#define FUSED_SMEM 230400

// ---------------- helpers ----------------
__device__ __forceinline__ uint32_t smem_u32(const void* p) {
    uint32_t a;
    asm("{ .reg .u64 t; cvta.to.shared.u64 t, %1; cvt.u32.u64 %0, t; }" : "=r"(a) : "l"(p));
    return a;
}
__device__ __forceinline__ void ldsm4(uint32_t* r, uint32_t addr) {
    asm volatile("ldmatrix.sync.aligned.m8n8.x4.shared.b16 {%0,%1,%2,%3}, [%4];"
                 : "=r"(r[0]), "=r"(r[1]), "=r"(r[2]), "=r"(r[3]) : "r"(addr));
}
__device__ __forceinline__ void mma16816(float* c, const uint32_t* a, const uint32_t* b) {
    asm volatile(
        "mma.sync.aligned.m16n8k16.row.col.f32.f16.f16.f32 "
        "{%0,%1,%2,%3}, {%4,%5,%6,%7}, {%8,%9}, {%0,%1,%2,%3};"
        : "+f"(c[0]), "+f"(c[1]), "+f"(c[2]), "+f"(c[3])
        : "r"(a[0]), "r"(a[1]), "r"(a[2]), "r"(a[3]), "r"(b[0]), "r"(b[1]));
}
__device__ __forceinline__ void cp16(uint32_t dst, const void* src) {
    asm volatile("cp.async.cg.shared.global [%0], [%1], 16;" :: "r"(dst), "l"(src));
}
__device__ __forceinline__ float tanha(float x) {
    float r;
    asm("tanh.approx.f32 %0, %1;" : "=f"(r) : "f"(x));
    return r;
}
__device__ __forceinline__ float sigt(float x) {
    return fmaf(tanha(0.5f * x), 0.5f, 0.5f);
}
__device__ __forceinline__ unsigned ld_acq(const unsigned* p) {
    unsigned v;
    asm volatile("ld.acquire.gpu.global.u32 %0, [%1];" : "=r"(v) : "l"(p) : "memory");
    return v;
}
#define BAR_LSTM() asm volatile("bar.sync 1, 256;" ::: "memory")

// ---------------- scratch ----------------
__device__ int   d_deg[NN];
__device__ int   d_rowptr[NN + 1];
__device__ int   d_cursor[NN];
__device__ int   d_csr[EE];
__device__ int   d_blocksum[128];
__device__ float d_dinv[NN];
__device__ unsigned d_flags[16];                  // [0..5]=h2 chunk done, [8..10]=h1 chunk done
__device__ __half d_xh[19200000];                 // [n][t*16+c]  (x * dinv[n])
__device__ __half d_h1[76800000];                 // [q][n][4t][64]   (h1 * dinv[n])
__device__ __half d_h2[76873728];                 // [t][NPAD][64] fp16
__device__ __half d_hst[6406144];                 // h state spill [NPAD][128]
__device__ float d_cst[6406144];                  // c state spill [tile][tid][16]
__device__ uint4 d_Bp[512 * 24];                  // fp16 weights, reordered cols

// ---------------- CSR build ----------------
__global__ void deg_kernel(const int* __restrict__ ei) {
    int e = blockIdx.x * 256 + threadIdx.x;
    if (e < EE) atomicAdd(&d_deg[ei[EE + e]], 1);
}
__global__ void dinv_scan_kernel() {
    __shared__ int s[512];
    int tid = threadIdx.x;
    int i = blockIdx.x * 512 + tid;
    int v = (i < NN) ? d_deg[i] : 0;
    if (i < NN) d_dinv[i] = rsqrtf((float)v + 1.0f);
    s[tid] = v;
    __syncthreads();
    #pragma unroll
    for (int off = 1; off < 512; off <<= 1) {
        int t = (tid >= off) ? s[tid - off] : 0;
        __syncthreads();
        s[tid] += t;
        __syncthreads();
    }
    if (i < NN) d_rowptr[i + 1] = s[tid];
    if (tid == 511) d_blocksum[blockIdx.x] = s[511];
}
__global__ void scan_add2_kernel() {
    __shared__ int soff;
    int sbk = blockIdx.x >> 1;
    if (threadIdx.x == 0) {
        int o = 0;
        for (int j = 0; j < sbk; j++) o += d_blocksum[j];
        soff = o;
    }
    __syncthreads();
    int i = blockIdx.x * 256 + threadIdx.x;
    if (i == 0) { d_rowptr[0] = 0; d_cursor[0] = 0; }
    if (i < NN) {
        int v = d_rowptr[i + 1] + soff;
        d_rowptr[i + 1] = v;
        if (i + 1 < NN) d_cursor[i + 1] = v;
    }
}

// ---------------- fused fill: csr_fill + xprep + bprep ----------------
__global__ void fused_fill_kernel(const int* __restrict__ ei,
                                  const float* __restrict__ x_seq,
                                  const float* __restrict__ Wih,
                                  const float* __restrict__ Whh) {
    int b = blockIdx.x;
    if (b < 6250) {
        int e = b * 256 + threadIdx.x;
        int s = ei[e];
        int d = ei[EE + e];
        int idx = atomicAdd(&d_cursor[d], 1);
        d_csr[idx] = s;
    } else if (b < 25000) {
        int id = (b - 6250) * 256 + threadIdx.x;
        if (id >= NN * 96) return;
        int n = id / 96, r = id % 96;
        int t = r >> 2, c4 = r & 3;
        float dn = d_dinv[n];
        float4 v = *(const float4*)(x_seq + ((size_t)t * NN + n) * F + c4 * 4);
        __half h[4] = {__float2half_rn(v.x * dn), __float2half_rn(v.y * dn),
                       __float2half_rn(v.z * dn), __float2half_rn(v.w * dn)};
        *(uint2*)(d_xh + (size_t)n * 384 + r * 4) = *(uint2*)h;
    } else {
        int id = (b - 25000) * 256 + threadIdx.x;
        if (id >= 512 * 24) return;
        int cg = id / 24, u = id % 24;
        int nb = cg >> 7, c = cg & 127;
        int wn = c >> 6, g = (c >> 4) & 3, jh = (c >> 3) & 1, s = c & 7;
        int jg = nb * 32 + wn * 16 + jh * 8 + s;
        int G = g * 128 + jg;
        union { __half h[8]; uint4 q; } up;
        #pragma unroll
        for (int e = 0; e < 8; e++) {
            int k = u * 8 + e;
            float v = (k < 64) ? Wih[G * 64 + k] : Whh[G * 128 + (k - 64)];
            up.h[e] = __float2half_rn(v);
        }
        d_Bp[(size_t)cg * 24 + u] = up.q;
    }
}

// ---------------- fused pipeline: agg1 -> agg2 producers + tile LSTM + FC ----------------
__global__ void __launch_bounds__(512, 1) fused_lstm(
    const float* __restrict__ bih, const float* __restrict__ bhh,
    const float* __restrict__ W1, const float* __restrict__ b1,
    const float* __restrict__ W2, const float* __restrict__ b2,
    const float* __restrict__ Wf1, const float* __restrict__ bf1,
    const float* __restrict__ Wf2, const float* __restrict__ bf2,
    float* __restrict__ out) {
    extern __shared__ char smem[];
    uint32_t sb = smem_u32(smem);
    const int tid = threadIdx.x, lane = tid & 31, wid = tid >> 5;
    const int cta = blockIdx.x;

    // one-time smem init (all 512 threads)
    for (int i = tid; i < 512 * 24; i += 512) {
        int col = i / 24, u = i % 24;
        *(uint4*)(smem + BOFF + col * 400 + u * 16) = d_Bp[(size_t)col * 24 + u];
    }
    __half* W2h = (__half*)(smem + W2HOFF);
    for (int i = tid; i < H * H; i += 512) W2h[i] = __float2half_rn(W2[i]);
    __half* W1h = (__half*)(smem + W1HOFF);
    for (int i = tid; i < F * H; i += 512) W1h[i] = __float2half_rn(W1[i]);
    float* b2s = (float*)(smem + B2OFF);
    if (tid < H) b2s[tid] = b2[tid];
    float* b1s = (float*)(smem + B1OFF);
    if (tid < H) b1s[tid] = b1[tid];
    float* bs = (float*)(smem + BIASOFF);
    if (tid < 512) bs[tid] = bih[tid] + bhh[tid];
    __syncthreads();

    if (wid >= 8) {
        // ================== PRODUCER ==================
        int pw = cta * 8 + (wid - 8);          // 0..1183
        const uint2* xr = (const uint2*)d_xh;
        const int t8 = lane >> 2, c4 = lane & 3;
        const __half2 hz = __floats2half2_rn(0.0f, 0.0f);

        // ---- phase 1: agg1 + mm1, three 8-t chunks ----
        for (int qq8 = 0; qq8 < 3; qq8++) {
            for (int n = pw; n < NN; n += NPROD) {
                float dn = d_dinv[n];
                uint2 u = xr[(size_t)n * 96 + qq8 * 32 + lane];
                float2 p0 = __half22float2(*(__half2*)&u.x);
                float2 p1 = __half22float2(*(__half2*)&u.y);
                float a0 = p0.x, a1 = p0.y, a2 = p1.x, a3 = p1.y;
                int e = d_rowptr[n], e1 = d_rowptr[n + 1];
                for (; e + 8 <= e1; e += 8) {
                    int si[8];
                    #pragma unroll
                    for (int k = 0; k < 8; k++) si[k] = d_csr[e + k];
                    uint2 v[8];
                    #pragma unroll
                    for (int k = 0; k < 8; k++)
                        v[k] = xr[(size_t)si[k] * 96 + qq8 * 32 + lane];
                    __half2 s0 = hz, s1 = hz;
                    #pragma unroll
                    for (int k = 0; k < 8; k++) {
                        s0 = __hadd2(s0, *(__half2*)&v[k].x);
                        s1 = __hadd2(s1, *(__half2*)&v[k].y);
                    }
                    float2 f0 = __half22float2(s0), f1 = __half22float2(s1);
                    a0 += f0.x; a1 += f0.y; a2 += f1.x; a3 += f1.y;
                }
                for (; e < e1; e++) {
                    uint2 v = xr[(size_t)d_csr[e] * 96 + qq8 * 32 + lane];
                    float2 q0 = __half22float2(*(__half2*)&v.x);
                    float2 q1 = __half22float2(*(__half2*)&v.y);
                    a0 += q0.x; a1 += q0.y; a2 += q1.x; a3 += q1.y;
                }
                float yv[4] = {a0 * dn, a1 * dn, a2 * dn, a3 * dn};
                // mm1: lane -> (t = t8, cols c4*16..c4*16+15); hfma2 blocks of 8 k
                float o[16];
                #pragma unroll
                for (int jj = 0; jj < 16; jj++) o[jj] = b1s[c4 * 16 + jj];
                #pragma unroll
                for (int kb = 0; kb < 2; kb++) {
                    __half2 oh[8];
                    #pragma unroll
                    for (int i = 0; i < 8; i++) oh[i] = hz;
                    #pragma unroll
                    for (int kk = 0; kk < 8; kk++) {
                        int k = kb * 8 + kk;
                        float yk = __shfl_sync(0xffffffffu, yv[k & 3], (t8 << 2) | (k >> 2));
                        __half2 z2 = __float2half2_rn(yk);
                        const __half2* wr = (const __half2*)(W1h + k * 64 + c4 * 16);
                        #pragma unroll
                        for (int i = 0; i < 8; i++) oh[i] = __hfma2(wr[i], z2, oh[i]);
                    }
                    #pragma unroll
                    for (int i = 0; i < 8; i++) {
                        float2 p = __half22float2(oh[i]);
                        o[2 * i] += p.x; o[2 * i + 1] += p.y;
                    }
                }
                __half hp[16];
                #pragma unroll
                for (int jj = 0; jj < 16; jj++)
                    hp[jj] = __float2half_rn(fmaxf(o[jj], 0.0f) * dn);
                int tg = qq8 * 8 + t8;
                __half* dst = d_h1 + (((size_t)(tg >> 2) * NN + n) * 4 + (tg & 3)) * 64 + c4 * 16;
                *(uint4*)dst = *(uint4*)hp;
                *(uint4*)(dst + 8) = *(uint4*)(hp + 8);
            }
            __threadfence();
            __syncwarp();
            if (lane == 0) atomicAdd(&d_flags[8 + qq8], 1u);
        }

        // ---- phase 2: agg2 + mm2, six 4-t chunks gated on h1 chunks ----
        int tt_o = lane >> 3, j8 = lane & 7, j0 = j8 * 8;
        float b2r[8];
        #pragma unroll
        for (int jj = 0; jj < 8; jj++) b2r[jj] = b2s[j0 + jj];
        for (int q = 0; q < 6; q++) {
            int qq8 = q >> 1;
            if (lane == 0) {
                while (ld_acq(&d_flags[8 + qq8]) < (unsigned)NPROD)
                    asm volatile("nanosleep.u32 128;");
            }
            __syncwarp();
            const uint4* h1q = (const uint4*)d_h1 + (size_t)q * NN * 32;
            for (int n = pw; n < NN; n += NPROD) {
                float dn = d_dinv[n];
                float acc[8];
                {
                    uint4 sv = h1q[(size_t)n * 32 + lane];
                    __half2* h = (__half2*)&sv;
                    #pragma unroll
                    for (int i = 0; i < 4; i++) {
                        float2 p = __half22float2(h[i]);
                        acc[2 * i] = p.x; acc[2 * i + 1] = p.y;
                    }
                }
                int e = d_rowptr[n], e1 = d_rowptr[n + 1];
                for (; e + 8 <= e1; e += 8) {
                    int si[8];
                    #pragma unroll
                    for (int u2 = 0; u2 < 8; u2++) si[u2] = d_csr[e + u2];
                    uint4 v[8];
                    #pragma unroll
                    for (int u2 = 0; u2 < 8; u2++) v[u2] = h1q[(size_t)si[u2] * 32 + lane];
                    __half2 ha[4];
                    #pragma unroll
                    for (int i = 0; i < 4; i++) ha[i] = hz;
                    #pragma unroll
                    for (int u2 = 0; u2 < 8; u2++) {
                        __half2* h = (__half2*)&v[u2];
                        #pragma unroll
                        for (int i = 0; i < 4; i++) ha[i] = __hadd2(ha[i], h[i]);
                    }
                    #pragma unroll
                    for (int i = 0; i < 4; i++) {
                        float2 p = __half22float2(ha[i]);
                        acc[2 * i] += p.x; acc[2 * i + 1] += p.y;
                    }
                }
                for (; e < e1; e++) {
                    uint4 v = h1q[(size_t)d_csr[e] * 32 + lane];
                    __half2* h = (__half2*)&v;
                    #pragma unroll
                    for (int i = 0; i < 4; i++) {
                        float2 p = __half22float2(h[i]);
                        acc[2 * i] += p.x; acc[2 * i + 1] += p.y;
                    }
                }
                #pragma unroll
                for (int i = 0; i < 8; i++) acc[i] *= dn;
                // mm2: hfma2 blocks of 16 k
                float o[8];
                #pragma unroll
                for (int jj = 0; jj < 8; jj++) o[jj] = b2r[jj];
                #pragma unroll
                for (int kb = 0; kb < 4; kb++) {
                    __half2 oh[4];
                    #pragma unroll
                    for (int i = 0; i < 4; i++) oh[i] = hz;
                    #pragma unroll
                    for (int kk = 0; kk < 16; kk++) {
                        int k = kb * 16 + kk;
                        float zk = __shfl_sync(0xffffffffu, acc[k & 7],
                                               (lane & 24) + (k >> 3));
                        __half2 z2 = __float2half2_rn(zk);
                        const __half2* wr = (const __half2*)(W2h + k * 64 + j0);
                        #pragma unroll
                        for (int i = 0; i < 4; i++) oh[i] = __hfma2(wr[i], z2, oh[i]);
                    }
                    #pragma unroll
                    for (int i = 0; i < 4; i++) {
                        float2 p = __half22float2(oh[i]);
                        o[2 * i] += p.x; o[2 * i + 1] += p.y;
                    }
                }
                __half hp[8];
                #pragma unroll
                for (int jj = 0; jj < 8; jj++)
                    hp[jj] = __float2half_rn(fmaxf(o[jj], 0.0f));
                *(uint4*)(d_h2 + ((size_t)(q * 4 + tt_o) * NPAD + n) * 64 + j0) = *(uint4*)hp;
            }
            __threadfence();
            __syncwarp();
            if (lane == 0) atomicAdd(&d_flags[q], 1u);
        }

        // ---- tail: zero d_deg for the next graph replay ----
        for (int i = pw * 32 + lane; i < NN; i += NPROD * 32) d_deg[i] = 0;
        return;
    }

    // ================== CONSUMER: tile LSTM, chunk-major ==================
    const int ntile = (cta < NTILES - NCTAS * 10) ? 11 : 10;   // 1564 = 84*11 + 64*10
    const int gq = lane >> 2, tq = lane & 3;
    const int q4 = lane >> 3, r8 = lane & 7;
    const uint32_t aRowOff = (uint32_t)(((q4 & 1) * 8 + r8) * 400 + ((q4 >> 1) * 8) * 2);
    const uint32_t bRowBase = (uint32_t)((wid * 64 + (q4 >> 1) * 8 + r8) * 400 + (q4 & 1) * 16);

    for (int q = 0; q < 6; q++) {
        if (tid == 0) {
            while (ld_acq(&d_flags[q]) < (unsigned)NPROD)
                asm volatile("nanosleep.u32 128;");
        }
        BAR_LSTM();

        for (int k = 0; k < ntile; k++) {
            int tile = cta + k * NCTAS;
            int row0 = tile * MTILE;
            {
                int row = tid >> 3, u = tid & 7;
                cp16(sb + AOFF + row * 400 + u * 16,
                     d_h2 + ((size_t)(q * 4) * NPAD + row0 + row) * 64 + u * 8);
            }
            asm volatile("cp.async.commit_group;" ::: "memory");
            float creg[16];
            if (q == 0) {
                #pragma unroll
                for (int i = 0; i < 16; i++) creg[i] = 0.0f;
                for (int i = tid; i < 512; i += 256) {
                    int row = i >> 4, u = i & 15;
                    *(uint4*)(smem + AOFF + row * 400 + 128 + u * 16) =
                        make_uint4(0, 0, 0, 0);
                }
            } else {
                const float4* cp4 = (const float4*)(d_cst + ((size_t)tile * 256 + tid) * 16);
                #pragma unroll
                for (int i = 0; i < 4; i++) {
                    float4 v = cp4[i];
                    creg[4 * i] = v.x; creg[4 * i + 1] = v.y;
                    creg[4 * i + 2] = v.z; creg[4 * i + 3] = v.w;
                }
                for (int i = tid; i < 512; i += 256) {
                    int row = i >> 4, u = i & 15;
                    *(uint4*)(smem + AOFF + row * 400 + 128 + u * 16) =
                        *(const uint4*)(d_hst + (size_t)(row0 + row) * 128 + u * 8);
                }
            }
            asm volatile("cp.async.wait_group 0;" ::: "memory");
            BAR_LSTM();

            for (int t = q * 4; t < q * 4 + 4; t++) {
                float acc[2][8][4];
                #pragma unroll
                for (int mi = 0; mi < 2; mi++)
                    #pragma unroll
                    for (int nt = 0; nt < 8; nt++)
                        #pragma unroll
                        for (int r = 0; r < 4; r++) acc[mi][nt][r] = 0.0f;

                uint32_t aB = sb + AOFF + aRowOff;
                uint32_t bB = sb + BOFF + bRowBase;
                #pragma unroll 1
                for (int ks = 0; ks < 12; ks++) {
                    uint32_t a[2][4];
                    ldsm4(a[0], aB + ks * 32);
                    ldsm4(a[1], aB + 16 * 400 + ks * 32);
                    #pragma unroll
                    for (int pr = 0; pr < 4; pr++) {
                        uint32_t t4[4];
                        ldsm4(t4, bB + pr * (16 * 400) + ks * 32);
                        uint32_t b0[2] = {t4[0], t4[1]};
                        uint32_t b1v[2] = {t4[2], t4[3]};
                        #pragma unroll
                        for (int mi = 0; mi < 2; mi++) {
                            mma16816(acc[mi][2 * pr], a[mi], b0);
                            mma16816(acc[mi][2 * pr + 1], a[mi], b1v);
                        }
                    }
                }
                BAR_LSTM();

                if (t + 1 < q * 4 + 4) {
                    int row = tid >> 3, u = tid & 7;
                    cp16(sb + AOFF + row * 400 + u * 16,
                         d_h2 + ((size_t)(t + 1) * NPAD + row0 + row) * 64 + u * 8);
                }
                asm volatile("cp.async.commit_group;" ::: "memory");

                #pragma unroll
                for (int mi = 0; mi < 2; mi++) {
                    #pragma unroll
                    for (int h = 0; h < 2; h++) {
                        int rl = mi * 16 + h * 8 + gq;
                        #pragma unroll
                        for (int jh = 0; jh < 2; jh++) {
                            int jl0 = jh * 8 + 2 * tq;
                            int jg0 = (wid >> 1) * 32 + (wid & 1) * 16 + jl0;
                            __half hout[2];
                            #pragma unroll
                            for (int p = 0; p < 2; p++) {
                                int jg = jg0 + p;
                                int ci = h * 2 + p;
                                float gi = acc[mi][0 + jh][ci] + bs[jg];
                                float gf = acc[mi][2 + jh][ci] + bs[128 + jg];
                                float gG = acc[mi][4 + jh][ci] + bs[256 + jg];
                                float go = acc[mi][6 + jh][ci] + bs[384 + jg];
                                int cidx = mi * 8 + h * 4 + jh * 2 + p;
                                float cn = sigt(gf) * creg[cidx] + sigt(gi) * tanha(gG);
                                creg[cidx] = cn;
                                hout[p] = __float2half_rn(sigt(go) * tanha(cn));
                            }
                            *(uint*)(smem + AOFF + rl * 400 + 128 + jg0 * 2) = *(uint*)hout;
                        }
                    }
                }
                asm volatile("cp.async.wait_group 0;" ::: "memory");
                BAR_LSTM();
            }

            if (q < 5) {
                float4* cp4 = (float4*)(d_cst + ((size_t)tile * 256 + tid) * 16);
                #pragma unroll
                for (int i = 0; i < 4; i++)
                    cp4[i] = make_float4(creg[4 * i], creg[4 * i + 1],
                                         creg[4 * i + 2], creg[4 * i + 3]);
                for (int i = tid; i < 512; i += 256) {
                    int row = i >> 4, u = i & 15;
                    *(uint4*)(d_hst + (size_t)(row0 + row) * 128 + u * 8) =
                        *(const uint4*)(smem + AOFF + row * 400 + 128 + u * 16);
                }
            } else {
                int node = tid >> 3, e8 = tid & 7;
                const __half* hrow = (const __half*)(smem + AOFF + node * 400 + 128);
                float part = 0.0f;
                #pragma unroll
                for (int jj = 0; jj < 4; jj++) {
                    int j = e8 * 4 + jj;
                    float z = __ldg(bf1 + j);
                    #pragma unroll 8
                    for (int kk = 0; kk < 128; kk++)
                        z = fmaf(__half2float(hrow[kk]), __ldg(Wf1 + kk * 32 + j), z);
                    part = fmaf(fmaxf(z, 0.0f), __ldg(Wf2 + j), part);
                }
                #pragma unroll
                for (int off = 4; off > 0; off >>= 1)
                    part += __shfl_down_sync(0xffffffffu, part, off, 8);
                int n = row0 + node;
                if (e8 == 0 && n < NN) out[n] = part + __ldg(bf2);
                BAR_LSTM();
            }
        }
    }
}

// ---------------- launcher ----------------
extern "C" void kernel_launch(void* const* d_in, const int* in_sizes, int n_in,
                              void* d_out, int out_size) {
    const float* x_seq = (const float*)d_in[0];
    const int*   ei    = (const int*)d_in[1];
    const float* W1    = (const float*)d_in[2];
    const float* b1    = (const float*)d_in[3];
    const float* W2    = (const float*)d_in[4];
    const float* b2    = (const float*)d_in[5];
    const float* Wih   = (const float*)d_in[6];
    const float* Whh   = (const float*)d_in[7];
    const float* bih   = (const float*)d_in[8];
    const float* bhh   = (const float*)d_in[9];
    const float* Wf1   = (const float*)d_in[10];
    const float* bf1   = (const float*)d_in[11];
    const float* Wf2   = (const float*)d_in[12];
    const float* bf2   = (const float*)d_in[13];
    float* out = (float*)d_out;

    cudaFuncSetAttribute(fused_lstm, cudaFuncAttributeMaxDynamicSharedMemorySize,
                         FUSED_SMEM);

    void* flagsp;
    cudaGetSymbolAddress(&flagsp, d_flags);
    cudaMemsetAsync(flagsp, 0, 16 * sizeof(unsigned));

    deg_kernel<<<(EE + 255) / 256, 256>>>(ei);
    dinv_scan_kernel<<<SCAN_NB, 512>>>();
    scan_add2_kernel<<<(NN + 255) / 256, 256>>>();
    fused_fill_kernel<<<25048, 256>>>(ei, x_seq, Wih, Whh);
    fused_lstm<<<NCTAS, 512, FUSED_SMEM>>>(
        bih, bhh, W1, b1, W2, b2, Wf1, bf1, Wf2, bf2, out);
}